// round 12
// baseline (speedup 1.0000x reference)
#include <cuda_runtime.h>
#include <cuda_fp16.h>
#include <cstdint>

// C[2048,4096] = A[2048,4096] @ W[4096,4096]^T + bias
// W dequantized from 4-bit codebook codes.
// R12: exact R8 kernel (BK=32, 3-stage cp.async, wait_group 1, tile 128x128,
// 4 warps, 64x64 warp tiles) but __launch_bounds__(128,3): regs capped so
// THREE CTAs/SM fit -> 3 independent barrier domains hide each other's
// sync/LDSM bubbles at unchanged per-mma smem cost.

constexpr int KDIM = 4096;
constexpr int NDIM = 4096;
constexpr int MDIM = 2048;

__device__ __half g_W[(size_t)NDIM * KDIM];   // dequantized fp16
__device__ __half g_A[(size_t)MDIM * KDIM];   // activations fp16

// ---------------------------------------------------------------------------
// Phase 1: merged prep. Blocks [0,4096): dequant W row. Blocks [4096,4608):
// convert x -> fp16.
// ---------------------------------------------------------------------------
constexpr int ACONV_BLOCKS = 512;
constexpr int ACHUNKS = MDIM * KDIM / 4;      // float4 chunks

__global__ void prep_kernel(const float* __restrict__ codebooks,
                            const int* __restrict__ codes,
                            const float* __restrict__ x) {
    if (blockIdx.x < NDIM) {
        const int r = blockIdx.x;
        __shared__ float cb[512];
        const float* cbr = codebooks + (size_t)r * 512;
        for (int i = threadIdx.x; i < 512; i += 256) cb[i] = cbr[i];
        __syncthreads();

        const int4* codes_r = (const int4*)(codes + (size_t)r * KDIM);
        __half2* w2 = (__half2*)(g_W + (size_t)r * KDIM);
        #pragma unroll
        for (int it = 0; it < 4; it++) {
            int i = threadIdx.x + it * 256;
            int4 c = codes_r[i];
            const float* cbg = cb + ((i >> 5) << 4);
            w2[2 * i]     = __floats2half2_rn(cbg[c.x], cbg[c.y]);
            w2[2 * i + 1] = __floats2half2_rn(cbg[c.z], cbg[c.w]);
        }
    } else {
        const int b = blockIdx.x - NDIM;
        __half2* a2 = (__half2*)g_A;
        #pragma unroll
        for (int it = 0; it < ACHUNKS / (ACONV_BLOCKS * 256); it++) {
            size_t i = (size_t)it * ACONV_BLOCKS * 256 + (size_t)b * 256 + threadIdx.x;
            const float4 v = ((const float4*)x)[i];
            a2[2 * i]     = __floats2half2_rn(v.x, v.y);
            a2[2 * i + 1] = __floats2half2_rn(v.z, v.w);
        }
    }
}

// ---------------------------------------------------------------------------
// Phase 2: fp16 mma.sync GEMM. Block 128x128x32(halfs), 4 warps,
// warp tile 64x64, 3-stage cp.async (wait_group 1), ldmatrix, 3 CTAs/SM.
// ---------------------------------------------------------------------------
constexpr int BM = 128, BN = 128, BK = 32;
constexpr int NTHREADS = 128;
constexpr int STRIDE = 40;                            // halfs; bank-bijective
constexpr int A_STAGE = BM * STRIDE;                  // 5120 halfs
constexpr int B_STAGE = BN * STRIDE;                  // 5120 halfs
constexpr int STAGE   = A_STAGE + B_STAGE;            // 10240 halfs (20480 B)
constexpr int NSTAGE  = 3;
constexpr int SMEM_DYN = STAGE * NSTAGE * 2;          // 61440 bytes
constexpr int KITERS = KDIM / BK;                     // 128

extern __shared__ __half smh[];

__device__ __forceinline__ uint32_t smem_u32(const void* p) {
    uint32_t a;
    asm("{ .reg .u64 t; cvta.to.shared.u64 t, %1; cvt.u32.u64 %0, t; }"
        : "=r"(a) : "l"(p));
    return a;
}

__device__ __forceinline__ void cp_async16(uint32_t dst, const void* src) {
    asm volatile("cp.async.cg.shared.global [%0], [%1], 16;"
                 :: "r"(dst), "l"(src));
}

__device__ __forceinline__ void ldmatrix_x4(uint32_t* r, uint32_t addr) {
    asm volatile(
        "ldmatrix.sync.aligned.m8n8.x4.shared.b16 {%0, %1, %2, %3}, [%4];"
        : "=r"(r[0]), "=r"(r[1]), "=r"(r[2]), "=r"(r[3])
        : "r"(addr));
}

__device__ __forceinline__ void mma_f16(float* c, const uint32_t* a,
                                        const uint32_t* b) {
    asm volatile(
        "mma.sync.aligned.m16n8k16.row.col.f32.f16.f16.f32 "
        "{%0,%1,%2,%3}, {%4,%5,%6,%7}, {%8,%9}, {%0,%1,%2,%3};"
        : "+f"(c[0]), "+f"(c[1]), "+f"(c[2]), "+f"(c[3])
        : "r"(a[0]), "r"(a[1]), "r"(a[2]), "r"(a[3]), "r"(b[0]), "r"(b[1]));
}

__device__ __forceinline__ void load_tile(uint32_t sbase,
                                          const __half* __restrict__ Ab,
                                          const __half* __restrict__ Bb,
                                          int k0, int tid) {
    // A: 128 rows x 4 chunks(8 halfs) = 512; 4 per thread
    #pragma unroll
    for (int j = 0; j < 4; j++) {
        int i = tid + j * NTHREADS;
        int row = i >> 2, c = (i & 3) * 8;
        cp_async16(sbase + (uint32_t)(row * STRIDE + c) * 2,
                   Ab + (size_t)row * KDIM + k0 + c);
    }
    // B: 128 rows x 4 chunks = 512; 4 per thread
    const uint32_t sb = sbase + A_STAGE * 2;
    #pragma unroll
    for (int j = 0; j < 4; j++) {
        int i = tid + j * NTHREADS;
        int row = i >> 2, c = (i & 3) * 8;
        cp_async16(sb + (uint32_t)(row * STRIDE + c) * 2,
                   Bb + (size_t)row * KDIM + k0 + c);
    }
    asm volatile("cp.async.commit_group;" ::: "memory");
}

__global__ void __launch_bounds__(NTHREADS, 3)
gemm_mma_kernel(const float* __restrict__ bias, float* __restrict__ C) {
    const int tid  = threadIdx.x;
    const int wid  = tid >> 5;
    const int lane = tid & 31;
    const int gid  = lane >> 2;      // group of 4
    const int tig  = lane & 3;       // thread in group

    const int m0 = blockIdx.y * BM;
    const int n0 = blockIdx.x * BN;
    const int wm = (wid >> 1) * 64;  // warp grid 2(M) x 2(N), tile 64x64
    const int wn = (wid & 1) * 64;

    const uint32_t smem_base = smem_u32(smh);
    const __half* Ab = g_A + (size_t)m0 * KDIM;
    const __half* Bb = g_W + (size_t)n0 * KDIM;

    // ldmatrix per-lane address offsets (bytes)
    const uint32_t a_lane = (uint32_t)((lane & 15) * STRIDE + ((lane >> 4) << 3)) * 2;
    const uint32_t b_lane = (uint32_t)((((lane >> 4) << 3) + (lane & 7)) * STRIDE
                                       + (lane & 8)) * 2;

    float acc[4][8][4] = {};

    load_tile(smem_base,             Ab, Bb, 0,  tid);
    load_tile(smem_base + STAGE * 2, Ab, Bb, BK, tid);

    for (int it = 0; it < KITERS; it++) {
        if (it + 1 < KITERS) {
            asm volatile("cp.async.wait_group 1;" ::: "memory");
        } else {
            asm volatile("cp.async.wait_group 0;" ::: "memory");
        }
        __syncthreads();

        if (it + 2 < KITERS) {
            load_tile(smem_base + (uint32_t)((it + 2) % NSTAGE) * STAGE * 2,
                      Ab, Bb, (it + 2) * BK, tid);
        }

        const uint32_t sA = smem_base + (uint32_t)(it % NSTAGE) * STAGE * 2;
        const uint32_t sB = sA + A_STAGE * 2;

        #pragma unroll
        for (int ks = 0; ks < 2; ks++) {            // 2 x K=16 steps
            const int kb = ks * 16;
            uint32_t af[4][4], bf[4][4];            // bf[p] covers nt=2p,2p+1
            #pragma unroll
            for (int mt = 0; mt < 4; mt++) {
                ldmatrix_x4(af[mt],
                            sA + (uint32_t)((wm + mt * 16) * STRIDE + kb) * 2
                               + a_lane);
            }
            #pragma unroll
            for (int p = 0; p < 4; p++) {
                ldmatrix_x4(bf[p],
                            sB + (uint32_t)((wn + p * 16) * STRIDE + kb) * 2
                               + b_lane);
            }
            #pragma unroll
            for (int mt = 0; mt < 4; mt++) {
                #pragma unroll
                for (int p = 0; p < 4; p++) {
                    mma_f16(acc[mt][2 * p],     af[mt], &bf[p][0]);
                    mma_f16(acc[mt][2 * p + 1], af[mt], &bf[p][2]);
                }
            }
        }
    }

    // epilogue: bias + store
    #pragma unroll
    for (int mt = 0; mt < 4; mt++) {
        #pragma unroll
        for (int nt = 0; nt < 8; nt++) {
            const int r0 = m0 + wm + mt * 16 + gid;
            const int c  = n0 + wn + nt * 8 + tig * 2;
            const float2 b2 = *(const float2*)(bias + c);
            float2 o0, o1;
            o0.x = acc[mt][nt][0] + b2.x;
            o0.y = acc[mt][nt][1] + b2.y;
            o1.x = acc[mt][nt][2] + b2.x;
            o1.y = acc[mt][nt][3] + b2.y;
            *(float2*)(C + (size_t)r0 * NDIM + c)       = o0;
            *(float2*)(C + (size_t)(r0 + 8) * NDIM + c) = o1;
        }
    }
}

// ---------------------------------------------------------------------------
extern "C" void kernel_launch(void* const* d_in, const int* in_sizes, int n_in,
                              void* d_out, int out_size) {
    const float* x         = (const float*)d_in[0];
    const float* codebooks = (const float*)d_in[1];
    const int*   codes     = (const int*)d_in[2];
    const float* bias      = (const float*)d_in[3];
    float* out = (float*)d_out;

    prep_kernel<<<NDIM + ACONV_BLOCKS, 256>>>(codebooks, codes, x);

    cudaFuncSetAttribute(gemm_mma_kernel,
                         cudaFuncAttributeMaxDynamicSharedMemorySize, SMEM_DYN);
    dim3 grid(NDIM / BN, MDIM / BM);   // (32, 16) = 512 blocks
    gemm_mma_kernel<<<grid, NTHREADS, SMEM_DYN>>>(bias, out);
}

// round 13
// speedup vs baseline: 1.1317x; 1.1317x over previous
#include <cuda_runtime.h>
#include <cuda_fp16.h>
#include <cstdint>

// C[2048,4096] = A[2048,4096] @ W[4096,4096]^T + bias
// W dequantized from 4-bit codebook codes.
// R13: R8 base (tile 128x128, BK=32, 4 warps, 64x64 warp tiles, 2 CTAs/SM)
// + cross-iteration fragment pipeline: frags for (it+1,ks0) prefetched during
// (it,ks1) mma so the tensor stream never waits on LDSM. 4 smem stages,
// wait_group 1 guarantees the prefetch source stage is complete.

constexpr int KDIM = 4096;
constexpr int NDIM = 4096;
constexpr int MDIM = 2048;

__device__ __half g_W[(size_t)NDIM * KDIM];   // dequantized fp16
__device__ __half g_A[(size_t)MDIM * KDIM];   // activations fp16

// ---------------------------------------------------------------------------
// Phase 1: merged prep. Blocks [0,4096): dequant W row. Blocks [4096,4608):
// convert x -> fp16.
// ---------------------------------------------------------------------------
constexpr int ACONV_BLOCKS = 512;
constexpr int ACHUNKS = MDIM * KDIM / 4;      // float4 chunks

__global__ void prep_kernel(const float* __restrict__ codebooks,
                            const int* __restrict__ codes,
                            const float* __restrict__ x) {
    if (blockIdx.x < NDIM) {
        const int r = blockIdx.x;
        __shared__ float cb[512];
        const float* cbr = codebooks + (size_t)r * 512;
        for (int i = threadIdx.x; i < 512; i += 256) cb[i] = cbr[i];
        __syncthreads();

        const int4* codes_r = (const int4*)(codes + (size_t)r * KDIM);
        __half2* w2 = (__half2*)(g_W + (size_t)r * KDIM);
        #pragma unroll
        for (int it = 0; it < 4; it++) {
            int i = threadIdx.x + it * 256;
            int4 c = codes_r[i];
            const float* cbg = cb + ((i >> 5) << 4);
            w2[2 * i]     = __floats2half2_rn(cbg[c.x], cbg[c.y]);
            w2[2 * i + 1] = __floats2half2_rn(cbg[c.z], cbg[c.w]);
        }
    } else {
        const int b = blockIdx.x - NDIM;
        __half2* a2 = (__half2*)g_A;
        #pragma unroll
        for (int it = 0; it < ACHUNKS / (ACONV_BLOCKS * 256); it++) {
            size_t i = (size_t)it * ACONV_BLOCKS * 256 + (size_t)b * 256 + threadIdx.x;
            const float4 v = ((const float4*)x)[i];
            a2[2 * i]     = __floats2half2_rn(v.x, v.y);
            a2[2 * i + 1] = __floats2half2_rn(v.z, v.w);
        }
    }
}

// ---------------------------------------------------------------------------
// Phase 2: fp16 mma.sync GEMM. Block 128x128x32(halfs), 4 warps,
// warp tile 64x64, 4-stage cp.async, cross-iter fragment pipeline, 2 CTAs/SM.
// ---------------------------------------------------------------------------
constexpr int BM = 128, BN = 128, BK = 32;
constexpr int NTHREADS = 128;
constexpr int STRIDE = 40;                            // halfs; bank-bijective
constexpr int A_STAGE = BM * STRIDE;                  // 5120 halfs
constexpr int B_STAGE = BN * STRIDE;                  // 5120 halfs
constexpr int STAGE   = A_STAGE + B_STAGE;            // 10240 halfs (20480 B)
constexpr int NSTAGE  = 4;
constexpr int SMEM_DYN = STAGE * NSTAGE * 2;          // 81920 bytes
constexpr int KITERS = KDIM / BK;                     // 128

extern __shared__ __half smh[];

__device__ __forceinline__ uint32_t smem_u32(const void* p) {
    uint32_t a;
    asm("{ .reg .u64 t; cvta.to.shared.u64 t, %1; cvt.u32.u64 %0, t; }"
        : "=r"(a) : "l"(p));
    return a;
}

__device__ __forceinline__ void cp_async16(uint32_t dst, const void* src) {
    asm volatile("cp.async.cg.shared.global [%0], [%1], 16;"
                 :: "r"(dst), "l"(src));
}

__device__ __forceinline__ void ldmatrix_x4(uint32_t* r, uint32_t addr) {
    asm volatile(
        "ldmatrix.sync.aligned.m8n8.x4.shared.b16 {%0, %1, %2, %3}, [%4];"
        : "=r"(r[0]), "=r"(r[1]), "=r"(r[2]), "=r"(r[3])
        : "r"(addr));
}

__device__ __forceinline__ void mma_f16(float* c, const uint32_t* a,
                                        const uint32_t* b) {
    asm volatile(
        "mma.sync.aligned.m16n8k16.row.col.f32.f16.f16.f32 "
        "{%0,%1,%2,%3}, {%4,%5,%6,%7}, {%8,%9}, {%0,%1,%2,%3};"
        : "+f"(c[0]), "+f"(c[1]), "+f"(c[2]), "+f"(c[3])
        : "r"(a[0]), "r"(a[1]), "r"(a[2]), "r"(a[3]), "r"(b[0]), "r"(b[1]));
}

__device__ __forceinline__ void load_tile(uint32_t sbase,
                                          const __half* __restrict__ Ab,
                                          const __half* __restrict__ Bb,
                                          int k0, int tid) {
    // A: 128 rows x 4 chunks(8 halfs) = 512; 4 per thread
    #pragma unroll
    for (int j = 0; j < 4; j++) {
        int i = tid + j * NTHREADS;
        int row = i >> 2, c = (i & 3) * 8;
        cp_async16(sbase + (uint32_t)(row * STRIDE + c) * 2,
                   Ab + (size_t)row * KDIM + k0 + c);
    }
    // B: 128 rows x 4 chunks = 512; 4 per thread
    const uint32_t sb = sbase + A_STAGE * 2;
    #pragma unroll
    for (int j = 0; j < 4; j++) {
        int i = tid + j * NTHREADS;
        int row = i >> 2, c = (i & 3) * 8;
        cp_async16(sb + (uint32_t)(row * STRIDE + c) * 2,
                   Bb + (size_t)row * KDIM + k0 + c);
    }
    asm volatile("cp.async.commit_group;" ::: "memory");
}

__global__ void __launch_bounds__(NTHREADS, 2)
gemm_mma_kernel(const float* __restrict__ bias, float* __restrict__ C) {
    const int tid  = threadIdx.x;
    const int wid  = tid >> 5;
    const int lane = tid & 31;
    const int gid  = lane >> 2;      // group of 4
    const int tig  = lane & 3;       // thread in group

    const int m0 = blockIdx.y * BM;
    const int n0 = blockIdx.x * BN;
    const int wm = (wid >> 1) * 64;  // warp grid 2(M) x 2(N), tile 64x64
    const int wn = (wid & 1) * 64;

    const uint32_t smem_base = smem_u32(smh);
    const __half* Ab = g_A + (size_t)m0 * KDIM;
    const __half* Bb = g_W + (size_t)n0 * KDIM;

    // ldmatrix per-lane address offsets (bytes)
    const uint32_t a_lane = (uint32_t)((lane & 15) * STRIDE + ((lane >> 4) << 3)) * 2;
    const uint32_t b_lane = (uint32_t)((((lane >> 4) << 3) + (lane & 7)) * STRIDE
                                       + (lane & 8)) * 2;

    float acc[4][8][4] = {};
    uint32_t af0[4][4], bf0[4][4], af1[4][4], bf1[4][4];

    auto load_frags = [&](uint32_t sA, uint32_t sB, int kb,
                          uint32_t (&af)[4][4], uint32_t (&bf)[4][4]) {
        #pragma unroll
        for (int mt = 0; mt < 4; mt++)
            ldmatrix_x4(af[mt],
                        sA + (uint32_t)((wm + mt * 16) * STRIDE + kb) * 2 + a_lane);
        #pragma unroll
        for (int p = 0; p < 4; p++)
            ldmatrix_x4(bf[p],
                        sB + (uint32_t)((wn + p * 16) * STRIDE + kb) * 2 + b_lane);
    };

    auto mma_block = [&](uint32_t (&af)[4][4], uint32_t (&bf)[4][4]) {
        #pragma unroll
        for (int mt = 0; mt < 4; mt++) {
            #pragma unroll
            for (int p = 0; p < 4; p++) {
                mma_f16(acc[mt][2 * p],     af[mt], &bf[p][0]);
                mma_f16(acc[mt][2 * p + 1], af[mt], &bf[p][2]);
            }
        }
    };

    // prologue: 3 stages in flight, then frags for (it0, ks0)
    load_tile(smem_base,                 Ab, Bb, 0,      tid);
    load_tile(smem_base + STAGE * 2,     Ab, Bb, BK,     tid);
    load_tile(smem_base + STAGE * 4,     Ab, Bb, 2 * BK, tid);
    asm volatile("cp.async.wait_group 2;" ::: "memory");
    __syncthreads();
    load_frags(smem_base, smem_base + A_STAGE * 2, 0, af0, bf0);

    for (int it = 0; it < KITERS; it++) {
        const uint32_t sA = smem_base + (uint32_t)(it % NSTAGE) * STAGE * 2;
        const uint32_t sB = sA + A_STAGE * 2;

        // ks0: prefetch frags for ks1, then mma on ks0 frags
        load_frags(sA, sB, 16, af1, bf1);
        mma_block(af0, bf0);

        // ks1: make stage it+1 visible, prefetch its ks0 frags, then mma
        if (it + 1 < KITERS) {
            asm volatile("cp.async.wait_group 1;" ::: "memory");
            __syncthreads();
            if (it + 3 < KITERS) {
                load_tile(smem_base + (uint32_t)((it + 3) % NSTAGE) * STAGE * 2,
                          Ab, Bb, (it + 3) * BK, tid);
            }
            const uint32_t nA = smem_base + (uint32_t)((it + 1) % NSTAGE) * STAGE * 2;
            load_frags(nA, nA + A_STAGE * 2, 0, af0, bf0);
        }
        mma_block(af1, bf1);
    }

    // epilogue: bias + store
    #pragma unroll
    for (int mt = 0; mt < 4; mt++) {
        #pragma unroll
        for (int nt = 0; nt < 8; nt++) {
            const int r0 = m0 + wm + mt * 16 + gid;
            const int c  = n0 + wn + nt * 8 + tig * 2;
            const float2 b2 = *(const float2*)(bias + c);
            float2 o0, o1;
            o0.x = acc[mt][nt][0] + b2.x;
            o0.y = acc[mt][nt][1] + b2.y;
            o1.x = acc[mt][nt][2] + b2.x;
            o1.y = acc[mt][nt][3] + b2.y;
            *(float2*)(C + (size_t)r0 * NDIM + c)       = o0;
            *(float2*)(C + (size_t)(r0 + 8) * NDIM + c) = o1;
        }
    }
}

// ---------------------------------------------------------------------------
extern "C" void kernel_launch(void* const* d_in, const int* in_sizes, int n_in,
                              void* d_out, int out_size) {
    const float* x         = (const float*)d_in[0];
    const float* codebooks = (const float*)d_in[1];
    const int*   codes     = (const int*)d_in[2];
    const float* bias      = (const float*)d_in[3];
    float* out = (float*)d_out;

    prep_kernel<<<NDIM + ACONV_BLOCKS, 256>>>(codebooks, codes, x);

    cudaFuncSetAttribute(gemm_mma_kernel,
                         cudaFuncAttributeMaxDynamicSharedMemorySize, SMEM_DYN);
    dim3 grid(NDIM / BN, MDIM / BM);   // (32, 16) = 512 blocks
    gemm_mma_kernel<<<grid, NTHREADS, SMEM_DYN>>>(bias, out);
}